// round 1
// baseline (speedup 1.0000x reference)
#include <cuda_runtime.h>

// CapsuleLayer fused kernel.
// x:      (4, 256, 14, 14) fp32          d_in[0]
// weight: (32, 288, 8, 16) fp32          d_in[1]   [o][k][i][c], k = kk*32+inc
// out:    (4, 512, 12, 12) fp32          d_out     channel = o*16 + c
//
// Block: 288 threads, handles one o and G=4 consecutive ow positions (same oh row).
// Thread tid owns route k=tid: inc = k%32, kk = k/32 (kh=kk/3, kw=kk%3).
// priors[g][c] (4x16) live in registers; routing reductions via warp butterflies + smem.

#define G 4
#define NTHREADS 288
#define NWARPS 9

// Reduce 16 values across the full warp with log-halving compaction.
// Input: red[0..15] per lane. Output: every lane l returns total sum for c = (l & 15).
__device__ __forceinline__ float reduce_warp16(float red[16], int lane)
{
    #pragma unroll
    for (int j = 0; j < 16; j++)
        red[j] += __shfl_xor_sync(0xffffffffu, red[j], 16);
    {
        const bool sel = (lane & 8) != 0;
        #pragma unroll
        for (int j = 0; j < 8; j++) {
            float mine  = sel ? red[j + 8] : red[j];
            float other = sel ? red[j]     : red[j + 8];
            other = __shfl_xor_sync(0xffffffffu, other, 8);
            red[j] = mine + other;
        }
    }
    {
        const bool sel = (lane & 4) != 0;
        #pragma unroll
        for (int j = 0; j < 4; j++) {
            float mine  = sel ? red[j + 4] : red[j];
            float other = sel ? red[j]     : red[j + 4];
            other = __shfl_xor_sync(0xffffffffu, other, 4);
            red[j] = mine + other;
        }
    }
    {
        const bool sel = (lane & 2) != 0;
        #pragma unroll
        for (int j = 0; j < 2; j++) {
            float mine  = sel ? red[j + 2] : red[j];
            float other = sel ? red[j]     : red[j + 2];
            other = __shfl_xor_sync(0xffffffffu, other, 2);
            red[j] = mine + other;
        }
    }
    {
        const bool sel = (lane & 1) != 0;
        float mine  = sel ? red[1] : red[0];
        float other = sel ? red[0] : red[1];
        other = __shfl_xor_sync(0xffffffffu, other, 1);
        red[0] = mine + other;
    }
    return red[0];  // = S[lane & 15]
}

__global__ __launch_bounds__(NTHREADS, 2)
void caps_kernel(const float* __restrict__ x,
                 const float* __restrict__ W,
                 float* __restrict__ out)
{
    __shared__ float xs[18 * 256];          // [pos = h'*6 + w'][ch]
    __shared__ float s_wsum[NWARPS][G];     // per-warp softmax partial sums
    __shared__ float s_wpart[NWARPS][G * 16]; // per-warp output partials
    __shared__ float s_vout[G * 16];        // squashed output vectors

    const int tid  = threadIdx.x;
    const int lane = tid & 31;
    const int warp = tid >> 5;

    const int o   = blockIdx.y;
    const int n0  = blockIdx.x * G;
    const int b   = n0 / 144;
    const int rr  = n0 - b * 144;
    const int oh  = rr / 12;
    const int ow0 = rr - oh * 12;

    // ---- Stage x patch into smem: ch in [0,256), h' in [0,3), w' in [0,6) ----
    {
        const float* xb = x + (size_t)b * (256 * 196);
        for (int r = tid; r < 768; r += NTHREADS) {
            const int ch = r & 255;
            const int hp = r >> 8;
            const float* src = xb + ch * 196 + (oh + hp) * 14 + ow0;
            float* dst = &xs[(hp * 6) * 256 + ch];
            #pragma unroll
            for (int wq = 0; wq < 6; wq++)
                dst[wq * 256] = __ldg(src + wq);
        }
    }
    __syncthreads();

    // ---- Per-thread route identity ----
    const int k     = tid;         // 0..287
    const int inc   = k & 31;
    const int kkpos = k >> 5;      // 0..8
    const int kh    = kkpos / 3;
    const int kw    = kkpos - kh * 3;
    const int pos0  = kh * 6 + kw;

    const float* Wo = W + ((size_t)o * 288 + k) * 128;   // [i][c] slab, 128 floats

    // ---- Priors GEMM: pr[g][c] = sum_i t[g][i] * W[o,k,i,c] ----
    float pr[G][16];
    #pragma unroll
    for (int g = 0; g < G; g++)
        #pragma unroll
        for (int c = 0; c < 16; c++)
            pr[g][c] = 0.0f;

    #pragma unroll
    for (int ii = 0; ii < 8; ii += 4) {
        float t0[G], t1[G], t2[G], t3[G];
        #pragma unroll
        for (int g = 0; g < G; g++) {
            const float4 v = *reinterpret_cast<const float4*>(
                &xs[(pos0 + g) * 256 + inc * 8 + ii]);
            t0[g] = v.x; t1[g] = v.y; t2[g] = v.z; t3[g] = v.w;
        }

        #define PROC_I(IOFF, T)                                               \
        {                                                                     \
            _Pragma("unroll")                                                 \
            for (int c4 = 0; c4 < 4; c4++) {                                  \
                const float4 w = __ldg(reinterpret_cast<const float4*>(       \
                    Wo + (ii + (IOFF)) * 16 + c4 * 4));                       \
                _Pragma("unroll")                                             \
                for (int g = 0; g < G; g++) {                                 \
                    pr[g][c4 * 4 + 0] = fmaf(w.x, T[g], pr[g][c4 * 4 + 0]);   \
                    pr[g][c4 * 4 + 1] = fmaf(w.y, T[g], pr[g][c4 * 4 + 1]);   \
                    pr[g][c4 * 4 + 2] = fmaf(w.z, T[g], pr[g][c4 * 4 + 2]);   \
                    pr[g][c4 * 4 + 3] = fmaf(w.w, T[g], pr[g][c4 * 4 + 3]);   \
                }                                                             \
            }                                                                 \
        }
        PROC_I(0, t0)
        PROC_I(1, t1)
        PROC_I(2, t2)
        PROC_I(3, t3)
        #undef PROC_I
    }

    // ---- Dynamic routing: 3 iterations ----
    float logit[G];
    #pragma unroll
    for (int g = 0; g < G; g++) logit[g] = 0.0f;

    for (int it = 0; it < 3; it++) {
        // 1) softmax over k (288 routes): exp + block-sum
        float e[G], sarr[G];
        #pragma unroll
        for (int g = 0; g < G; g++) {
            e[g] = __expf(logit[g]);
            float s = e[g];
            s += __shfl_xor_sync(0xffffffffu, s, 16);
            s += __shfl_xor_sync(0xffffffffu, s, 8);
            s += __shfl_xor_sync(0xffffffffu, s, 4);
            s += __shfl_xor_sync(0xffffffffu, s, 2);
            s += __shfl_xor_sync(0xffffffffu, s, 1);
            sarr[g] = s;
        }
        if (lane == 0) {
            #pragma unroll
            for (int g = 0; g < G; g++) s_wsum[warp][g] = sarr[g];
        }
        __syncthreads();

        float p[G];
        #pragma unroll
        for (int g = 0; g < G; g++) {
            float d = 0.0f;
            #pragma unroll
            for (int w = 0; w < NWARPS; w++) d += s_wsum[w][g];
            p[g] = __fdividef(e[g], d);
        }

        // 2) weighted sum over routes: out[c] = sum_k p_k * pr[k][c]
        #pragma unroll
        for (int g = 0; g < G; g++) {
            float red[16];
            #pragma unroll
            for (int c = 0; c < 16; c++) red[c] = p[g] * pr[g][c];
            const float r0 = reduce_warp16(red, lane);
            if (lane < 16) s_wpart[warp][g * 16 + lane] = r0;
        }
        __syncthreads();

        // 3) warp 0 finalizes: cross-warp sum + squash (+ final store)
        if (warp == 0) {
            #pragma unroll
            for (int g = 0; g < G; g++) {
                float val = 0.0f;
                if (lane < 16) {
                    #pragma unroll
                    for (int w = 0; w < NWARPS; w++)
                        val += s_wpart[w][g * 16 + lane];
                }
                float sq = val * val;
                sq += __shfl_xor_sync(0xffffffffu, sq, 8);
                sq += __shfl_xor_sync(0xffffffffu, sq, 4);
                sq += __shfl_xor_sync(0xffffffffu, sq, 2);
                sq += __shfl_xor_sync(0xffffffffu, sq, 1);
                // squash: v = s * sqrt(sq) / (1 + sq)
                const float scale = __fdividef(sqrtf(sq), 1.0f + sq);
                const float ov = val * scale;
                if (it == 2) {
                    if (lane < 16) {
                        out[(size_t)(b * 512 + o * 16 + lane) * 144
                            + oh * 12 + ow0 + g] = ov;
                    }
                } else {
                    if (lane < 16) s_vout[g * 16 + lane] = ov;
                }
            }
        }

        // 4) logits += priors . v
        if (it < 2) {
            __syncthreads();
            #pragma unroll
            for (int g = 0; g < G; g++) {
                float acc = 0.0f;
                #pragma unroll
                for (int c = 0; c < 16; c++)
                    acc = fmaf(pr[g][c], s_vout[g * 16 + c], acc);
                logit[g] += acc;
            }
        }
    }
}

extern "C" void kernel_launch(void* const* d_in, const int* in_sizes, int n_in,
                              void* d_out, int out_size)
{
    (void)in_sizes; (void)n_in; (void)out_size;
    const float* x = (const float*)d_in[0];
    const float* w = (const float*)d_in[1];
    float* out = (float*)d_out;

    dim3 grid(144, 32);   // 576/G n-groups  x  32 output caps
    caps_kernel<<<grid, NTHREADS>>>(x, w, out);
}

// round 2
// speedup vs baseline: 1.4005x; 1.4005x over previous
#include <cuda_runtime.h>

// CapsuleLayer fused kernel, round 2: lane-interleaved weight repack.
// x:      (4, 256, 14, 14) fp32          d_in[0]
// weight: (32, 288, 8, 16) fp32          d_in[1]   [o][k][i][c], k = kk*32+inc
// out:    (4, 512, 12, 12) fp32          d_out     channel = o*16 + c
//
// Pre-kernel repacks W into Wt[o][kw][i][c4][lane][4] so the main kernel's
// per-warp weight loads are 512B-contiguous (4 wavefronts per LDG.128 instead of 32).

#define G 4
#define NTHREADS 288
#define NWARPS 9

// Repacked weights: 32 o * 9 kw * 8 i * 4 c4 * 32 lane * 4 floats = 1,179,648 floats
__device__ float g_Wt[32 * 9 * 8 * 4 * 32 * 4];

__global__ void repack_kernel(const float* __restrict__ W)
{
    // one float4 per thread; src float4 index = ((o*288+k)*8+i)*4+c4
    const int idx = blockIdx.x * 256 + threadIdx.x;   // 0 .. 294911
    const int c4 = idx & 3;
    const int i  = (idx >> 2) & 7;
    const int t  = idx >> 5;
    const int k  = t % 288;
    const int o  = t / 288;
    const int kw = k >> 5;
    const int ln = k & 31;
    const int dst4 = (((o * 9 + kw) * 8 + i) * 4 + c4) * 32 + ln;
    reinterpret_cast<float4*>(g_Wt)[dst4] =
        reinterpret_cast<const float4*>(W)[idx];
}

// Reduce 16 values across the full warp with log-halving compaction.
// Input: red[0..15] per lane. Output: lane l returns total sum for c = (l & 15).
__device__ __forceinline__ float reduce_warp16(float red[16], int lane)
{
    #pragma unroll
    for (int j = 0; j < 16; j++)
        red[j] += __shfl_xor_sync(0xffffffffu, red[j], 16);
    {
        const bool sel = (lane & 8) != 0;
        #pragma unroll
        for (int j = 0; j < 8; j++) {
            float mine  = sel ? red[j + 8] : red[j];
            float other = sel ? red[j]     : red[j + 8];
            other = __shfl_xor_sync(0xffffffffu, other, 8);
            red[j] = mine + other;
        }
    }
    {
        const bool sel = (lane & 4) != 0;
        #pragma unroll
        for (int j = 0; j < 4; j++) {
            float mine  = sel ? red[j + 4] : red[j];
            float other = sel ? red[j]     : red[j + 4];
            other = __shfl_xor_sync(0xffffffffu, other, 4);
            red[j] = mine + other;
        }
    }
    {
        const bool sel = (lane & 2) != 0;
        #pragma unroll
        for (int j = 0; j < 2; j++) {
            float mine  = sel ? red[j + 2] : red[j];
            float other = sel ? red[j]     : red[j + 2];
            other = __shfl_xor_sync(0xffffffffu, other, 2);
            red[j] = mine + other;
        }
    }
    {
        const bool sel = (lane & 1) != 0;
        float mine  = sel ? red[1] : red[0];
        float other = sel ? red[0] : red[1];
        other = __shfl_xor_sync(0xffffffffu, other, 1);
        red[0] = mine + other;
    }
    return red[0];  // = S[lane & 15]
}

__global__ __launch_bounds__(NTHREADS, 2)
void caps_kernel(const float* __restrict__ x,
                 float* __restrict__ out)
{
    __shared__ float xs[18 * 256];            // [pos = h'*6 + w'][ch]
    __shared__ float s_wsum[NWARPS][G];       // per-warp softmax partial sums
    __shared__ float s_wpart[NWARPS][G * 16]; // per-warp output partials
    __shared__ float s_vout[G * 16];          // squashed output vectors

    const int tid  = threadIdx.x;
    const int lane = tid & 31;
    const int warp = tid >> 5;

    const int o   = blockIdx.y;
    const int n0  = blockIdx.x * G;
    const int b   = n0 / 144;
    const int rr  = n0 - b * 144;
    const int oh  = rr / 12;
    const int ow0 = rr - oh * 12;

    // ---- Stage x patch into smem: ch in [0,256), h' in [0,3), w' in [0,6) ----
    {
        const float* xb = x + (size_t)b * (256 * 196);
        for (int r = tid; r < 768; r += NTHREADS) {
            const int ch = r & 255;
            const int hp = r >> 8;
            const float* src = xb + ch * 196 + (oh + hp) * 14 + ow0;
            float* dst = &xs[(hp * 6) * 256 + ch];
            #pragma unroll
            for (int wq = 0; wq < 6; wq++)
                dst[wq * 256] = __ldg(src + wq);
        }
    }
    __syncthreads();

    // ---- Per-thread route identity: k = tid, kw = warp, ln = lane ----
    const int kkpos = warp;            // 0..8 (kernel tap)
    const int kh    = kkpos / 3;
    const int kw3   = kkpos - kh * 3;
    const int pos0  = kh * 6 + kw3;

    // Per-thread weight base in repacked layout:
    // float offset = (o*9+warp)*4096 + (i*4+c4)*128 + lane*4
    const float* Wtb = g_Wt + ((size_t)(o * 9 + warp) * 4096) + lane * 4;

    // ---- Priors GEMM: pr[g][c] = sum_i t[g][i] * W[o,k,i,c] ----
    float pr[G][16];
    #pragma unroll
    for (int g = 0; g < G; g++)
        #pragma unroll
        for (int c = 0; c < 16; c++)
            pr[g][c] = 0.0f;

    #pragma unroll
    for (int ii = 0; ii < 8; ii += 4) {
        float t0[G], t1[G], t2[G], t3[G];
        #pragma unroll
        for (int g = 0; g < G; g++) {
            const float4 v = *reinterpret_cast<const float4*>(
                &xs[(pos0 + g) * 256 + lane * 8 + ii]);
            t0[g] = v.x; t1[g] = v.y; t2[g] = v.z; t3[g] = v.w;
        }

        #define PROC_I(IOFF, T)                                               \
        {                                                                     \
            _Pragma("unroll")                                                 \
            for (int c4 = 0; c4 < 4; c4++) {                                  \
                const float4 w = *reinterpret_cast<const float4*>(            \
                    Wtb + ((ii + (IOFF)) * 4 + c4) * 128);                    \
                _Pragma("unroll")                                             \
                for (int g = 0; g < G; g++) {                                 \
                    pr[g][c4 * 4 + 0] = fmaf(w.x, T[g], pr[g][c4 * 4 + 0]);   \
                    pr[g][c4 * 4 + 1] = fmaf(w.y, T[g], pr[g][c4 * 4 + 1]);   \
                    pr[g][c4 * 4 + 2] = fmaf(w.z, T[g], pr[g][c4 * 4 + 2]);   \
                    pr[g][c4 * 4 + 3] = fmaf(w.w, T[g], pr[g][c4 * 4 + 3]);   \
                }                                                             \
            }                                                                 \
        }
        PROC_I(0, t0)
        PROC_I(1, t1)
        PROC_I(2, t2)
        PROC_I(3, t3)
        #undef PROC_I
    }

    // ---- Dynamic routing: 3 iterations ----
    float logit[G];
    #pragma unroll
    for (int g = 0; g < G; g++) logit[g] = 0.0f;

    for (int it = 0; it < 3; it++) {
        // 1) softmax over k (288 routes): exp + block-sum
        float e[G], sarr[G];
        #pragma unroll
        for (int g = 0; g < G; g++) {
            e[g] = __expf(logit[g]);
            float s = e[g];
            s += __shfl_xor_sync(0xffffffffu, s, 16);
            s += __shfl_xor_sync(0xffffffffu, s, 8);
            s += __shfl_xor_sync(0xffffffffu, s, 4);
            s += __shfl_xor_sync(0xffffffffu, s, 2);
            s += __shfl_xor_sync(0xffffffffu, s, 1);
            sarr[g] = s;
        }
        if (lane == 0) {
            #pragma unroll
            for (int g = 0; g < G; g++) s_wsum[warp][g] = sarr[g];
        }
        __syncthreads();

        float p[G];
        #pragma unroll
        for (int g = 0; g < G; g++) {
            float d = 0.0f;
            #pragma unroll
            for (int w = 0; w < NWARPS; w++) d += s_wsum[w][g];
            p[g] = __fdividef(e[g], d);
        }

        // 2) weighted sum over routes: out[c] = sum_k p_k * pr[k][c]
        #pragma unroll
        for (int g = 0; g < G; g++) {
            float red[16];
            #pragma unroll
            for (int c = 0; c < 16; c++) red[c] = p[g] * pr[g][c];
            const float r0 = reduce_warp16(red, lane);
            if (lane < 16) s_wpart[warp][g * 16 + lane] = r0;
        }
        __syncthreads();

        // 3) warp 0 finalizes: cross-warp sum + squash (+ final store)
        if (warp == 0) {
            #pragma unroll
            for (int g = 0; g < G; g++) {
                float val = 0.0f;
                if (lane < 16) {
                    #pragma unroll
                    for (int w = 0; w < NWARPS; w++)
                        val += s_wpart[w][g * 16 + lane];
                }
                float sq = val * val;
                sq += __shfl_xor_sync(0xffffffffu, sq, 8);
                sq += __shfl_xor_sync(0xffffffffu, sq, 4);
                sq += __shfl_xor_sync(0xffffffffu, sq, 2);
                sq += __shfl_xor_sync(0xffffffffu, sq, 1);
                // squash: v = s * sqrt(sq) / (1 + sq)
                const float scale = __fdividef(sqrtf(sq), 1.0f + sq);
                const float ov = val * scale;
                if (it == 2) {
                    if (lane < 16) {
                        out[(size_t)(b * 512 + o * 16 + lane) * 144
                            + oh * 12 + ow0 + g] = ov;
                    }
                } else {
                    if (lane < 16) s_vout[g * 16 + lane] = ov;
                }
            }
        }

        // 4) logits += priors . v
        if (it < 2) {
            __syncthreads();
            #pragma unroll
            for (int g = 0; g < G; g++) {
                float acc = 0.0f;
                #pragma unroll
                for (int c = 0; c < 16; c++)
                    acc = fmaf(pr[g][c], s_vout[g * 16 + c], acc);
                logit[g] += acc;
            }
        }
    }
}

extern "C" void kernel_launch(void* const* d_in, const int* in_sizes, int n_in,
                              void* d_out, int out_size)
{
    (void)in_sizes; (void)n_in; (void)out_size;
    const float* x = (const float*)d_in[0];
    const float* w = (const float*)d_in[1];
    float* out = (float*)d_out;

    repack_kernel<<<1152, 256>>>(w);           // 294912 float4s

    dim3 grid(144, 32);   // 576/G n-groups  x  32 output caps
    caps_kernel<<<grid, NTHREADS>>>(x, out);
}

// round 4
// speedup vs baseline: 1.5844x; 1.1314x over previous
#include <cuda_runtime.h>

// CapsuleLayer fused kernel, round 3: repack BOTH weights and x tiles so the
// main kernel issues only warp-contiguous LDG.128 (no smem staging).
// x:      (4, 256, 14, 14) fp32          d_in[0]
// weight: (32, 288, 8, 16) fp32          d_in[1]   [o][k][i][c], k = kk*32+inc
// out:    (4, 512, 12, 12) fp32          d_out     channel = o*16 + c

#define G 4
#define NTHREADS 288
#define NWARPS 9

// Repacked weights: Wt[o][kk][i][c4][lane][4] : 32*9*8*4*32*4 floats
__device__ float g_Wt[32 * 9 * 8 * 4 * 32 * 4];
// Repacked x tiles: T[n][kk][lane=inc][i] : 576*9*32*8 floats = 5.3MB
__device__ float g_tiles[576 * 9 * 32 * 8];

__global__ void repack_kernel(const float* __restrict__ W)
{
    const int idx = blockIdx.x * 256 + threadIdx.x;   // 0 .. 294911 float4s
    const int c4 = idx & 3;
    const int i  = (idx >> 2) & 7;
    const int t  = idx >> 5;
    const int k  = t % 288;
    const int o  = t / 288;
    const int kk = k >> 5;
    const int ln = k & 31;
    const int dst4 = (((o * 9 + kk) * 8 + i) * 4 + c4) * 32 + ln;
    reinterpret_cast<float4*>(g_Wt)[dst4] =
        reinterpret_cast<const float4*>(W)[idx];
}

__global__ void tile_kernel(const float* __restrict__ x)
{
    const int idx = blockIdx.x * 256 + threadIdx.x;   // 0 .. 331775 float4s
    const int ihalf = idx & 1;
    const int lane  = (idx >> 1) & 31;
    const int t     = idx >> 6;        // n*9 + kk, 0..5183
    const int kk    = t % 9;
    const int n     = t / 9;
    const int b     = n / 144;
    const int rr    = n - b * 144;
    const int oh    = rr / 12;
    const int ow    = rr - oh * 12;
    const int kh    = kk / 3;
    const int kw    = kk - kh * 3;

    const float* src = x + (size_t)b * (256 * 196)
                         + (size_t)(lane * 8 + ihalf * 4) * 196
                         + (oh + kh) * 14 + (ow + kw);
    float4 v;
    v.x = __ldg(src);
    v.y = __ldg(src + 196);
    v.z = __ldg(src + 392);
    v.w = __ldg(src + 588);
    reinterpret_cast<float4*>(g_tiles)[idx] = v;
}

// Reduce 16 values across the full warp with log-halving compaction.
// Input: red[0..15] per lane. Output: lane l returns total sum for c = (l & 15).
__device__ __forceinline__ float reduce_warp16(float red[16], int lane)
{
    #pragma unroll
    for (int j = 0; j < 16; j++)
        red[j] += __shfl_xor_sync(0xffffffffu, red[j], 16);
    {
        const bool sel = (lane & 8) != 0;
        #pragma unroll
        for (int j = 0; j < 8; j++) {
            float mine  = sel ? red[j + 8] : red[j];
            float other = sel ? red[j]     : red[j + 8];
            other = __shfl_xor_sync(0xffffffffu, other, 8);
            red[j] = mine + other;
        }
    }
    {
        const bool sel = (lane & 4) != 0;
        #pragma unroll
        for (int j = 0; j < 4; j++) {
            float mine  = sel ? red[j + 4] : red[j];
            float other = sel ? red[j]     : red[j + 4];
            other = __shfl_xor_sync(0xffffffffu, other, 4);
            red[j] = mine + other;
        }
    }
    {
        const bool sel = (lane & 2) != 0;
        #pragma unroll
        for (int j = 0; j < 2; j++) {
            float mine  = sel ? red[j + 2] : red[j];
            float other = sel ? red[j]     : red[j + 2];
            other = __shfl_xor_sync(0xffffffffu, other, 2);
            red[j] = mine + other;
        }
    }
    {
        const bool sel = (lane & 1) != 0;
        float mine  = sel ? red[1] : red[0];
        float other = sel ? red[0] : red[1];
        other = __shfl_xor_sync(0xffffffffu, other, 1);
        red[0] = mine + other;
    }
    return red[0];  // = S[lane & 15]
}

__global__ __launch_bounds__(NTHREADS, 2)
void caps_kernel(float* __restrict__ out)
{
    __shared__ float s_wsum[NWARPS][G];       // per-warp softmax partial sums
    __shared__ float s_wpart[NWARPS][G * 16]; // per-warp output partials
    __shared__ float s_vout[G * 16];          // squashed output vectors

    const int tid  = threadIdx.x;
    const int lane = tid & 31;
    const int warp = tid >> 5;

    const int o   = blockIdx.y;
    const int n0  = blockIdx.x * G;
    const int b   = n0 / 144;
    const int rr  = n0 - b * 144;
    const int oh  = rr / 12;
    const int ow0 = rr - oh * 12;

    // Per-thread weight base in repacked layout:
    // float offset = (o*9+warp)*4096 + (i*4+c4)*128 + lane*4
    const float* Wtb = g_Wt + ((size_t)(o * 9 + warp) * 4096) + lane * 4;
    // Per-thread tile base: ((n*9+warp)*32+lane)*8
    const float* Tb0 = g_tiles + (((size_t)n0 * 9 + warp) * 32 + lane) * 8;

    // ---- Priors GEMM: pr[g][c] = sum_i t[g][i] * W[o,k,i,c] ----
    float pr[G][16];
    #pragma unroll
    for (int g = 0; g < G; g++)
        #pragma unroll
        for (int c = 0; c < 16; c++)
            pr[g][c] = 0.0f;

    #pragma unroll
    for (int ii = 0; ii < 8; ii += 4) {
        float t0[G], t1[G], t2[G], t3[G];
        #pragma unroll
        for (int g = 0; g < G; g++) {
            const float4 v = __ldg(reinterpret_cast<const float4*>(
                Tb0 + (size_t)g * (9 * 32 * 8) + ii));
            t0[g] = v.x; t1[g] = v.y; t2[g] = v.z; t3[g] = v.w;
        }

        #define PROC_I(IOFF, T)                                               \
        {                                                                     \
            _Pragma("unroll")                                                 \
            for (int c4 = 0; c4 < 4; c4++) {                                  \
                const float4 w = *reinterpret_cast<const float4*>(            \
                    Wtb + ((ii + (IOFF)) * 4 + c4) * 128);                    \
                _Pragma("unroll")                                             \
                for (int g = 0; g < G; g++) {                                 \
                    pr[g][c4 * 4 + 0] = fmaf(w.x, T[g], pr[g][c4 * 4 + 0]);   \
                    pr[g][c4 * 4 + 1] = fmaf(w.y, T[g], pr[g][c4 * 4 + 1]);   \
                    pr[g][c4 * 4 + 2] = fmaf(w.z, T[g], pr[g][c4 * 4 + 2]);   \
                    pr[g][c4 * 4 + 3] = fmaf(w.w, T[g], pr[g][c4 * 4 + 3]);   \
                }                                                             \
            }                                                                 \
        }
        PROC_I(0, t0)
        PROC_I(1, t1)
        PROC_I(2, t2)
        PROC_I(3, t3)
        #undef PROC_I
    }

    // ---- Dynamic routing: 3 iterations ----
    float logit[G];
    #pragma unroll
    for (int g = 0; g < G; g++) logit[g] = 0.0f;

    for (int it = 0; it < 3; it++) {
        // 1) softmax over k (288 routes): exp + block-sum
        float e[G], sarr[G];
        #pragma unroll
        for (int g = 0; g < G; g++) {
            e[g] = __expf(logit[g]);
            float s = e[g];
            s += __shfl_xor_sync(0xffffffffu, s, 16);
            s += __shfl_xor_sync(0xffffffffu, s, 8);
            s += __shfl_xor_sync(0xffffffffu, s, 4);
            s += __shfl_xor_sync(0xffffffffu, s, 2);
            s += __shfl_xor_sync(0xffffffffu, s, 1);
            sarr[g] = s;
        }
        if (lane == 0) {
            #pragma unroll
            for (int g = 0; g < G; g++) s_wsum[warp][g] = sarr[g];
        }
        __syncthreads();

        float p[G];
        #pragma unroll
        for (int g = 0; g < G; g++) {
            float d = 0.0f;
            #pragma unroll
            for (int w = 0; w < NWARPS; w++) d += s_wsum[w][g];
            p[g] = __fdividef(e[g], d);
        }

        // 2) weighted sum over routes: out[c] = sum_k p_k * pr[k][c]
        #pragma unroll
        for (int g = 0; g < G; g++) {
            float red[16];
            #pragma unroll
            for (int c = 0; c < 16; c++) red[c] = p[g] * pr[g][c];
            const float r0 = reduce_warp16(red, lane);
            if (lane < 16) s_wpart[warp][g * 16 + lane] = r0;
        }
        __syncthreads();

        // 3) warp 0 finalizes: cross-warp sum + squash (+ final store)
        if (warp == 0) {
            #pragma unroll
            for (int g = 0; g < G; g++) {
                float val = 0.0f;
                if (lane < 16) {
                    #pragma unroll
                    for (int w = 0; w < NWARPS; w++)
                        val += s_wpart[w][g * 16 + lane];
                }
                float sq = val * val;
                sq += __shfl_xor_sync(0xffffffffu, sq, 8);
                sq += __shfl_xor_sync(0xffffffffu, sq, 4);
                sq += __shfl_xor_sync(0xffffffffu, sq, 2);
                sq += __shfl_xor_sync(0xffffffffu, sq, 1);
                // squash: v = s * sqrt(sq) / (1 + sq)
                const float scale = __fdividef(sqrtf(sq), 1.0f + sq);
                const float ov = val * scale;
                if (it == 2) {
                    if (lane < 16) {
                        out[(size_t)(b * 512 + o * 16 + lane) * 144
                            + oh * 12 + ow0 + g] = ov;
                    }
                } else {
                    if (lane < 16) s_vout[g * 16 + lane] = ov;
                }
            }
        }

        // 4) logits += priors . v
        if (it < 2) {
            __syncthreads();
            #pragma unroll
            for (int g = 0; g < G; g++) {
                float acc = 0.0f;
                #pragma unroll
                for (int c = 0; c < 16; c++)
                    acc = fmaf(pr[g][c], s_vout[g * 16 + c], acc);
                logit[g] += acc;
            }
        }
    }
}

extern "C" void kernel_launch(void* const* d_in, const int* in_sizes, int n_in,
                              void* d_out, int out_size)
{
    (void)in_sizes; (void)n_in; (void)out_size;
    const float* x = (const float*)d_in[0];
    const float* w = (const float*)d_in[1];
    float* out = (float*)d_out;

    repack_kernel<<<1152, 256>>>(w);   // 294912 float4s
    tile_kernel<<<1296, 256>>>(x);     // 331776 float4s

    dim3 grid(144, 32);   // 576/G n-groups  x  32 output caps
    caps_kernel<<<grid, NTHREADS>>>(out);
}